// round 1
// baseline (speedup 1.0000x reference)
#include <cuda_runtime.h>

#define N_NODES 20000
#define N_EDGES 200000
#define D 32
#define R 100
#define EPS 1e-5f
#define MAXWL 8192

// ---------------- device scratch (no allocations allowed) ----------------
__device__ float g_cnt[N_NODES];          // per-dst edge counts
__device__ int   g_hist[R];               // per-relation edge counts
__device__ int   g_off[R + 1];            // exclusive scan of hist
__device__ int   g_cursor[R];             // scatter cursors
__device__ int   g_chunkbase[R + 1];      // worklist entry base per relation
__device__ int   g_perm[N_EDGES];         // edge ids sorted by etype
__device__ float g_sum[D], g_sumsq[D];    // batchnorm stats accumulators
__device__ float g_scale[D], g_shift[D];  // folded BN affine
__device__ int   g_nchunk;
__device__ int   g_wl_r[MAXWL], g_wl_s[MAXWL], g_wl_n[MAXWL];

// ---------------- K0: zero everything that accumulates ----------------
__global__ void k0_zero(float* __restrict__ out) {
    int i = blockIdx.x * blockDim.x + threadIdx.x;
    int stride = gridDim.x * blockDim.x;
    for (int j = i; j < N_NODES * D; j += stride) out[j] = 0.f;
    for (int j = i; j < N_NODES; j += stride) g_cnt[j] = 0.f;
    if (i < D) { g_sum[i] = 0.f; g_sumsq[i] = 0.f; }
    if (i < R) g_hist[i] = 0;
}

// ---------------- K1: histogram of etype ----------------
__global__ void k1_hist(const int* __restrict__ etype) {
    __shared__ int sh[R];
    for (int i = threadIdx.x; i < R; i += blockDim.x) sh[i] = 0;
    __syncthreads();
    int i = blockIdx.x * blockDim.x + threadIdx.x;
    for (int e = i; e < N_EDGES; e += gridDim.x * blockDim.x)
        atomicAdd(&sh[etype[e]], 1);
    __syncthreads();
    for (int j = threadIdx.x; j < R; j += blockDim.x)
        if (sh[j]) atomicAdd(&g_hist[j], sh[j]);
}

// ---------------- K2: scan + worklist build (single block) ----------------
__global__ void k2_scan() {
    if (threadIdx.x == 0) {
        int acc = 0, cacc = 0;
        for (int r = 0; r < R; r++) {
            g_off[r] = acc;
            g_cursor[r] = acc;
            g_chunkbase[r] = cacc;
            int c = g_hist[r];
            acc += c;
            cacc += (c + 31) / 32;
        }
        g_off[R] = acc;
        g_chunkbase[R] = cacc;
        g_nchunk = cacc;
    }
    __syncthreads();
    // parallel worklist fill: one thread per relation
    for (int r = threadIdx.x; r < R; r += blockDim.x) {
        int s = g_off[r], e2 = g_off[r + 1], w = g_chunkbase[r];
        for (int p = s; p < e2; p += 32) {
            g_wl_r[w] = r;
            g_wl_s[w] = p;
            g_wl_n[w] = min(32, e2 - p);
            w++;
        }
    }
}

// ---------------- K3: scatter edges into sorted order ----------------
__global__ void k3_scatter(const int* __restrict__ etype) {
    int i = blockIdx.x * blockDim.x + threadIdx.x;
    for (int e = i; e < N_EDGES; e += gridDim.x * blockDim.x) {
        int pos = atomicAdd(&g_cursor[etype[e]], 1);
        g_perm[pos] = e;
    }
}

// ---------------- K4/K6: the main pass (PASS=0 stats, PASS=1 scatter) ----
// One warp handles a worklist entry: up to 32 edges of a single relation r.
// Lane d holds column d of W[r] in registers (32 regs), so per edge we do
// one coalesced h-row load + 32 shfl broadcasts + 32 FFMA.
template <int PASS>
__global__ void __launch_bounds__(128) k_pass(
    const float* __restrict__ h, const float* __restrict__ weight,
    const int* __restrict__ src, const int* __restrict__ dst,
    float* __restrict__ out)
{
    const int lane = threadIdx.x & 31;
    const int warp = (blockIdx.x * blockDim.x + threadIdx.x) >> 5;
    const int nwarp = (gridDim.x * blockDim.x) >> 5;
    const int nchunk = g_nchunk;

    float lsum = 0.f, lsq = 0.f;
    float sc = 0.f, shf = 0.f;
    if (PASS == 1) { sc = g_scale[lane]; shf = g_shift[lane]; }

    for (int w = warp; w < nchunk; w += nwarp) {
        int r = g_wl_r[w], s = g_wl_s[w], n = g_wl_n[w];
        const float* wp = weight + r * (D * D) + lane;
        float wc[32];
#pragma unroll
        for (int k = 0; k < 32; k++) wc[k] = wp[k * 32];

        int e = -1, sj = 0, dj = 0;
        if (lane < n) { e = g_perm[s + lane]; sj = src[e]; dj = dst[e]; }
        if (PASS == 0 && e >= 0) atomicAdd(&g_cnt[dj], 1.0f);

        for (int j = 0; j < n; j++) {
            int sje = __shfl_sync(0xffffffffu, sj, j);
            float hv = h[sje * D + lane];  // coalesced 128B row load
            float a0 = 0.f, a1 = 0.f, a2 = 0.f, a3 = 0.f;
#pragma unroll
            for (int k = 0; k < 32; k += 4) {
                a0 = fmaf(__shfl_sync(0xffffffffu, hv, k + 0), wc[k + 0], a0);
                a1 = fmaf(__shfl_sync(0xffffffffu, hv, k + 1), wc[k + 1], a1);
                a2 = fmaf(__shfl_sync(0xffffffffu, hv, k + 2), wc[k + 2], a2);
                a3 = fmaf(__shfl_sync(0xffffffffu, hv, k + 3), wc[k + 3], a3);
            }
            float acc = fmaxf((a0 + a1) + (a2 + a3), 0.f);
            if (PASS == 0) {
                lsum += acc;
                lsq = fmaf(acc, acc, lsq);
            } else {
                int dje = __shfl_sync(0xffffffffu, dj, j);
                atomicAdd(&out[dje * D + lane], fmaf(acc, sc, shf));
            }
        }
    }
    if (PASS == 0) {
        atomicAdd(&g_sum[lane], lsum);
        atomicAdd(&g_sumsq[lane], lsq);
    }
}

// ---------------- K5: finalize batchnorm affine ----------------
__global__ void k5_final(const float* __restrict__ gamma,
                         const float* __restrict__ beta) {
    int d = threadIdx.x;
    if (d < D) {
        float inv_e = 1.0f / (float)N_EDGES;
        float mu = g_sum[d] * inv_e;
        float var = fmaxf(g_sumsq[d] * inv_e - mu * mu, 0.f);
        float rs = rsqrtf(var + EPS);
        float scale = rs * gamma[d];
        g_scale[d] = scale;
        g_shift[d] = beta[d] - mu * scale;
    }
}

// ---------------- K7: divide by counts (segment mean) ----------------
__global__ void k7_div(float* __restrict__ out) {
    int i = blockIdx.x * blockDim.x + threadIdx.x;
    for (int j = i; j < N_NODES * D; j += gridDim.x * blockDim.x) {
        out[j] = out[j] / fmaxf(g_cnt[j >> 5], 1.0f);  // D == 32
    }
}

extern "C" void kernel_launch(void* const* d_in, const int* in_sizes, int n_in,
                              void* d_out, int out_size) {
    const float* h      = (const float*)d_in[0];
    const float* weight = (const float*)d_in[1];
    const float* gamma  = (const float*)d_in[2];
    const float* beta   = (const float*)d_in[3];
    const int*   src    = (const int*)d_in[4];
    const int*   dst    = (const int*)d_in[5];
    const int*   etype  = (const int*)d_in[6];
    float* out = (float*)d_out;

    k0_zero<<<512, 256>>>(out);
    k1_hist<<<256, 256>>>(etype);
    k2_scan<<<1, 128>>>();
    k3_scatter<<<256, 256>>>(etype);
    k_pass<0><<<1600, 128>>>(h, weight, src, dst, out);
    k5_final<<<1, 32>>>(gamma, beta);
    k_pass<1><<<1600, 128>>>(h, weight, src, dst, out);
    k7_div<<<512, 256>>>(out);
}

// round 2
// speedup vs baseline: 1.2233x; 1.2233x over previous
#include <cuda_runtime.h>

#define N_NODES 20000
#define N_EDGES 200000
#define D 32
#define R 100
#define EPS 1e-5f
#define MAXWL 8192
#define NB 200          // histogram/scatter blocks
#define EPB 1000        // edges per block (NB*EPB == N_EDGES)

// ---------------- device scratch (static, no runtime allocation) --------
__device__ float g_cnt[N_NODES];            // per-dst edge counts
__device__ int   g_bh[R * NB];              // per-(relation, block) histogram
__device__ int   g_boff[R * NB];            // per-(relation, block) base offset
__device__ int   g_hist[R];                 // per-relation totals
__device__ int   g_off[R + 1];              // exclusive scan of g_hist
__device__ int   g_chunkbase[R + 1];
__device__ int   g_ssrc[N_EDGES];           // src sorted by etype
__device__ int   g_sdst[N_EDGES];           // dst sorted by etype
__device__ float g_msg[N_EDGES * D];        // relu(h[src] @ W[etype]) in sorted order
__device__ float g_sum[D], g_sumsq[D];
__device__ float g_scale[D], g_shift[D];
__device__ int   g_nchunk;
__device__ int   g_wl_r[MAXWL], g_wl_s[MAXWL], g_wl_n[MAXWL];

// ---------------- K0: zero accumulators ----------------
__global__ void k0_zero(float* __restrict__ out) {
    int i = blockIdx.x * blockDim.x + threadIdx.x;
    int stride = gridDim.x * blockDim.x;
    for (int j = i; j < N_NODES * D; j += stride) out[j] = 0.f;
    for (int j = i; j < N_NODES; j += stride) g_cnt[j] = 0.f;
    if (i < D) { g_sum[i] = 0.f; g_sumsq[i] = 0.f; }
}

// ---------------- K1: per-block histograms (atomic-free globally) -------
__global__ void __launch_bounds__(256) k1_hist(const int* __restrict__ etype) {
    __shared__ int sh[R];
    for (int i = threadIdx.x; i < R; i += blockDim.x) sh[i] = 0;
    __syncthreads();
    int base = blockIdx.x * EPB;
    for (int i = threadIdx.x; i < EPB; i += blockDim.x)
        atomicAdd(&sh[etype[base + i]], 1);
    __syncthreads();
    for (int r = threadIdx.x; r < R; r += blockDim.x)
        g_bh[r * NB + blockIdx.x] = sh[r];
}

// ---------------- K2: 2D scan + worklist (single block) ------------------
__global__ void __launch_bounds__(128) k2_scan() {
    int t = threadIdx.x;
    // phase A: per-relation scan over blocks
    for (int r = t; r < R; r += blockDim.x) {
        int acc = 0;
        for (int b = 0; b < NB; b++) {
            g_boff[r * NB + b] = acc;
            acc += g_bh[r * NB + b];
        }
        g_hist[r] = acc;
    }
    __syncthreads();
    // phase B: scan relations
    if (t == 0) {
        int acc = 0, cacc = 0;
        for (int r = 0; r < R; r++) {
            g_off[r] = acc;
            g_chunkbase[r] = cacc;
            acc += g_hist[r];
            cacc += (g_hist[r] + 31) / 32;
        }
        g_off[R] = acc;
        g_chunkbase[R] = cacc;
        g_nchunk = cacc;
    }
    __syncthreads();
    // phase C: offset block bases by relation base; build worklist
    for (int r = t; r < R; r += blockDim.x) {
        int o = g_off[r];
        for (int b = 0; b < NB; b++) g_boff[r * NB + b] += o;
        int s = g_off[r], e2 = g_off[r + 1], w = g_chunkbase[r];
        for (int p = s; p < e2; p += 32) {
            g_wl_r[w] = r; g_wl_s[w] = p; g_wl_n[w] = min(32, e2 - p);
            w++;
        }
    }
}

// ---------------- K3: scatter with SHARED cursors only -------------------
__global__ void __launch_bounds__(256) k3_scatter(
    const int* __restrict__ etype, const int* __restrict__ src,
    const int* __restrict__ dst)
{
    __shared__ int cur[R];
    for (int r = threadIdx.x; r < R; r += blockDim.x)
        cur[r] = g_boff[r * NB + blockIdx.x];
    __syncthreads();
    int base = blockIdx.x * EPB;
    for (int i = threadIdx.x; i < EPB; i += blockDim.x) {
        int e = base + i;
        int pos = atomicAdd(&cur[etype[e]], 1);
        g_ssrc[pos] = src[e];
        int dj = dst[e];
        g_sdst[pos] = dj;
        atomicAdd(&g_cnt[dj], 1.0f);   // 200K atomics over 20K addrs: fine
    }
}

// ---------------- K4: GEMV pass — compute msg + batch stats --------------
// One warp = one 32-edge chunk of a single relation. Lane d holds column d
// of W[r] in registers; per edge: 1 coalesced h-row LDG + shfl-broadcast FMA.
__global__ void __launch_bounds__(128) k4_compute(
    const float* __restrict__ h, const float* __restrict__ weight)
{
    const int lane = threadIdx.x & 31;
    const int wid  = threadIdx.x >> 5;
    const int warp = (blockIdx.x * blockDim.x + threadIdx.x) >> 5;
    const int nwarp = (gridDim.x * blockDim.x) >> 5;
    const int nchunk = g_nchunk;

    float lsum = 0.f, lsq = 0.f;

    for (int w = warp; w < nchunk; w += nwarp) {
        int r = g_wl_r[w], s = g_wl_s[w], n = g_wl_n[w];
        const float* wp = weight + r * (D * D) + lane;
        float wc[32];
#pragma unroll
        for (int k = 0; k < 32; k++) wc[k] = wp[k * 32];

        int sj = 0;
        if (lane < n) sj = g_ssrc[s + lane];

        for (int j = 0; j < n; j++) {
            int sje = __shfl_sync(0xffffffffu, sj, j);
            float hv = h[sje * D + lane];
            float a0 = 0.f, a1 = 0.f, a2 = 0.f, a3 = 0.f;
#pragma unroll
            for (int k = 0; k < 32; k += 4) {
                a0 = fmaf(__shfl_sync(0xffffffffu, hv, k + 0), wc[k + 0], a0);
                a1 = fmaf(__shfl_sync(0xffffffffu, hv, k + 1), wc[k + 1], a1);
                a2 = fmaf(__shfl_sync(0xffffffffu, hv, k + 2), wc[k + 2], a2);
                a3 = fmaf(__shfl_sync(0xffffffffu, hv, k + 3), wc[k + 3], a3);
            }
            float acc = fmaxf((a0 + a1) + (a2 + a3), 0.f);
            lsum += acc;
            lsq = fmaf(acc, acc, lsq);
            g_msg[(s + j) * D + lane] = acc;   // coalesced 128B store
        }
    }
    // block-level reduce, then one warp does the global atomics
    __shared__ float ssum[4][32], ssq[4][32];
    ssum[wid][lane] = lsum; ssq[wid][lane] = lsq;
    __syncthreads();
    if (wid == 0) {
        float ts = ssum[0][lane] + ssum[1][lane] + ssum[2][lane] + ssum[3][lane];
        float tq = ssq[0][lane] + ssq[1][lane] + ssq[2][lane] + ssq[3][lane];
        atomicAdd(&g_sum[lane], ts);
        atomicAdd(&g_sumsq[lane], tq);
    }
}

// ---------------- K5: fold batchnorm into affine scale/shift -------------
__global__ void k5_final(const float* __restrict__ gamma,
                         const float* __restrict__ beta) {
    int d = threadIdx.x;
    if (d < D) {
        float inv_e = 1.0f / (float)N_EDGES;
        float mu = g_sum[d] * inv_e;
        float var = fmaxf(g_sumsq[d] * inv_e - mu * mu, 0.f);
        float scale = rsqrtf(var + EPS) * gamma[d];
        g_scale[d] = scale;
        g_shift[d] = beta[d] - mu * scale;
    }
}

// ---------------- K6: BN-apply + scatter into dst nodes ------------------
__global__ void __launch_bounds__(128) k6_scatter(float* __restrict__ out) {
    const int lane = threadIdx.x & 31;
    const int warp = (blockIdx.x * blockDim.x + threadIdx.x) >> 5;
    const int nwarp = (gridDim.x * blockDim.x) >> 5;
    const float sc = g_scale[lane], shf = g_shift[lane];

    for (int p = warp; p < N_EDGES; p += nwarp) {
        int dj;
        if (lane == 0) dj = g_sdst[p];
        dj = __shfl_sync(0xffffffffu, dj, 0);
        float v = fmaf(g_msg[p * D + lane], sc, shf);  // coalesced L2 read
        atomicAdd(&out[dj * D + lane], v);
    }
}

// ---------------- K7: divide by counts (segment mean) --------------------
__global__ void k7_div(float* __restrict__ out) {
    int i = blockIdx.x * blockDim.x + threadIdx.x;
    for (int j = i; j < N_NODES * D; j += gridDim.x * blockDim.x)
        out[j] = out[j] / fmaxf(g_cnt[j >> 5], 1.0f);   // D == 32
}

extern "C" void kernel_launch(void* const* d_in, const int* in_sizes, int n_in,
                              void* d_out, int out_size) {
    const float* h      = (const float*)d_in[0];
    const float* weight = (const float*)d_in[1];
    const float* gamma  = (const float*)d_in[2];
    const float* beta   = (const float*)d_in[3];
    const int*   src    = (const int*)d_in[4];
    const int*   dst    = (const int*)d_in[5];
    const int*   etype  = (const int*)d_in[6];
    float* out = (float*)d_out;

    k0_zero<<<512, 256>>>(out);
    k1_hist<<<NB, 256>>>(etype);
    k2_scan<<<1, 128>>>();
    k3_scatter<<<NB, 256>>>(etype, src, dst);
    k4_compute<<<1600, 128>>>(h, weight);
    k5_final<<<1, 32>>>(gamma, beta);
    k6_scatter<<<1600, 128>>>(out);
    k7_div<<<512, 256>>>(out);
}